// round 2
// baseline (speedup 1.0000x reference)
#include <cuda_runtime.h>

// LocalizationLoss fused single-pass reduction, single kernel launch.
// output: (B, 3, 7) f32 ; target: (B, 3, 5) f32 [presence, x, y, wh, cls]
// loss = 0.5 + mean_{b,n}[ 5*lx^2 + 5*ly^2 + 10*lwh^2 + 3*nll - 0.5*bce_term ]

#define B_TOTAL   1048576
#define NANCH     3
#define OC        7    // output channels
#define TC        5    // target channels
#define TPB       256  // threads per block == batches per block
#define NBLOCKS   (B_TOTAL / TPB)   // 4096

__device__ float        g_partials[NBLOCKS];
__device__ unsigned int g_count;   // zero-initialized; wraps back to 0 every run

__global__ void __launch_bounds__(TPB) ll_main_kernel(const float* __restrict__ gout,
                                                      const float* __restrict__ gtgt,
                                                      float* __restrict__ out) {
    __shared__ float sOut[TPB * NANCH * OC];   // 21504 B
    __shared__ float sTgt[TPB * NANCH * TC];   // 15360 B
    __shared__ float wsum[TPB / 32];
    __shared__ bool  isLast;

    const int tid = threadIdx.x;
    const long long blockBase = (long long)blockIdx.x * TPB;

    // -------- coalesced float4 staging, streaming hint (no reuse) --------
    const float4* g4o = reinterpret_cast<const float4*>(gout + blockBase * (NANCH * OC));
    const float4* g4t = reinterpret_cast<const float4*>(gtgt + blockBase * (NANCH * TC));
    float4* s4o = reinterpret_cast<float4*>(sOut);
    float4* s4t = reinterpret_cast<float4*>(sTgt);

    constexpr int N4O = TPB * NANCH * OC / 4;  // 1344
    constexpr int N4T = TPB * NANCH * TC / 4;  //  960
    #pragma unroll
    for (int i = tid; i < N4O; i += TPB) s4o[i] = __ldcs(&g4o[i]);
    #pragma unroll
    for (int i = tid; i < N4T; i += TPB) s4t[i] = __ldcs(&g4t[i]);
    __syncthreads();

    // -------- per-batch loss terms (strides 21/15 are odd -> no bank conflicts) --------
    const float* o  = sOut + tid * (NANCH * OC);
    const float* tg = sTgt + tid * (NANCH * TC);

    float acc = 0.0f;
    float l[NANCH][3];   // masked class logits, l[anchor][class]
    int   cls[NANCH];

    #pragma unroll
    for (int n = 0; n < NANCH; n++) {
        const float p = o[n * OC + 0];
        const float t = tg[n * TC + 0];

        // bce term: t*log(p) + (1-t)*log(1-p)
        const float bce = t * __logf(p) + (1.0f - t) * __logf(1.0f - p);

        const float mask = (t != 0.0f) ? 1.0f : 0.0f;

        const float lx = mask * o[n * OC + 1] - tg[n * TC + 1];
        const float ly = mask * o[n * OC + 2] - tg[n * TC + 2];

        // sq_pred = mask ? sqrt(out_wh) : 0   (out_wh in (0,1), sqrt always valid)
        const float sp  = mask * __fsqrt_rn(o[n * OC + 3]);
        const float lwh = sp - __fsqrt_rn(tg[n * TC + 3]);

        acc += 5.0f * (lx * lx + ly * ly) + 10.0f * (lwh * lwh) - 0.5f * bce;

        cls[n] = (int)tg[n * TC + 4];
        #pragma unroll
        for (int c = 0; c < 3; c++) l[n][c] = mask * o[n * OC + 4 + c];
    }

    // log_softmax over anchors (axis=1) per class column, then NLL gather
    #pragma unroll
    for (int c = 0; c < 3; c++) {
        const float m = fmaxf(l[0][c], fmaxf(l[1][c], l[2][c]));
        const float s = __expf(l[0][c] - m) + __expf(l[1][c] - m) + __expf(l[2][c] - m);
        const float lse = m + __logf(s);
        const float sel = (cls[c] == 0) ? l[0][c] : ((cls[c] == 1) ? l[1][c] : l[2][c]);
        acc += 3.0f * (lse - sel);
    }

    // -------- block reduction --------
    #pragma unroll
    for (int off = 16; off > 0; off >>= 1)
        acc += __shfl_xor_sync(0xFFFFFFFFu, acc, off);
    if ((tid & 31) == 0) wsum[tid >> 5] = acc;
    __syncthreads();

    if (tid == 0) {
        float s = 0.0f;
        #pragma unroll
        for (int w = 0; w < TPB / 32; w++) s += wsum[w];
        g_partials[blockIdx.x] = s;
        __threadfence();
        // atomicInc wraps to 0 when reaching NBLOCKS-1 -> self-resetting, graph-replay safe
        unsigned int prev = atomicInc(&g_count, NBLOCKS - 1);
        isLast = (prev == NBLOCKS - 1);
    }
    __syncthreads();

    // -------- last block reduces all partials and writes the scalar --------
    if (isLast) {
        double d = 0.0;
        for (int i = tid; i < NBLOCKS; i += TPB) d += (double)g_partials[i];
        // double shuffle reduce within warp
        #pragma unroll
        for (int off = 16; off > 0; off >>= 1)
            d += __shfl_xor_sync(0xFFFFFFFFu, d, off);
        __shared__ double dsum[TPB / 32];
        if ((tid & 31) == 0) dsum[tid >> 5] = d;
        __syncthreads();
        if (tid == 0) {
            double tot = 0.0;
            #pragma unroll
            for (int w = 0; w < TPB / 32; w++) tot += dsum[w];
            out[0] = (float)(0.5 + tot / (double)((long long)B_TOTAL * NANCH));
        }
    }
}

extern "C" void kernel_launch(void* const* d_in, const int* in_sizes, int n_in,
                              void* d_out, int out_size) {
    // Identify inputs by element count (output: B*21, target: B*15)
    const float* gout = (const float*)d_in[0];
    const float* gtgt = (const float*)d_in[1];
    if (n_in >= 2 && in_sizes[0] == B_TOTAL * NANCH * TC) {
        gout = (const float*)d_in[1];
        gtgt = (const float*)d_in[0];
    }

    ll_main_kernel<<<NBLOCKS, TPB>>>(gout, gtgt, (float*)d_out);
}

// round 3
// speedup vs baseline: 1.1576x; 1.1576x over previous
#include <cuda_runtime.h>

// LocalizationLoss fused single-pass reduction, single launch, persistent blocks.
// output: (B, 3, 7) f32 ; target: (B, 3, 5) f32 [presence, x, y, wh, cls]
// loss = 0.5 + mean_{b,n}[ 5*lx^2 + 5*ly^2 + 10*lwh^2 + 3*nll - 0.5*bce_term ]

#define B_TOTAL   1048576
#define NANCH     3
#define OC        7    // output channels
#define TC        5    // target channels
#define TPB       256  // threads per block == batches per tile
#define NTILES    (B_TOTAL / TPB)   // 4096
#define GRID      888               // 148 SMs x 6 CTAs (smem/reg occupancy limit)

__device__ double       g_acc;     // zero at load; reset by last block each run
__device__ unsigned int g_count;   // wraps back to 0 via atom.inc

__global__ void __launch_bounds__(TPB) ll_main_kernel(const float* __restrict__ gout,
                                                      const float* __restrict__ gtgt,
                                                      float* __restrict__ out) {
    __shared__ float sOut[TPB * NANCH * OC];   // 21504 B
    __shared__ float sTgt[TPB * NANCH * TC];   // 15360 B
    __shared__ float wsum[TPB / 32];
    __shared__ bool  isLast;

    const int tid = threadIdx.x;
    float acc = 0.0f;

    constexpr int N4O = TPB * NANCH * OC / 4;  // 1344
    constexpr int N4T = TPB * NANCH * TC / 4;  //  960
    float4* s4o = reinterpret_cast<float4*>(sOut);
    float4* s4t = reinterpret_cast<float4*>(sTgt);

    // -------- grid-stride over 256-batch tiles --------
    for (int tile = blockIdx.x; tile < NTILES; tile += GRID) {
        const long long blockBase = (long long)tile * TPB;
        const float4* g4o = reinterpret_cast<const float4*>(gout + blockBase * (NANCH * OC));
        const float4* g4t = reinterpret_cast<const float4*>(gtgt + blockBase * (NANCH * TC));

        #pragma unroll
        for (int i = tid; i < N4O; i += TPB) s4o[i] = g4o[i];
        #pragma unroll
        for (int i = tid; i < N4T; i += TPB) s4t[i] = g4t[i];
        __syncthreads();

        // per-batch loss terms (strides 21/15 odd -> conflict-free)
        const float* o  = sOut + tid * (NANCH * OC);
        const float* tg = sTgt + tid * (NANCH * TC);

        float l[NANCH][3];
        int   cls[NANCH];

        #pragma unroll
        for (int n = 0; n < NANCH; n++) {
            const float p = o[n * OC + 0];
            const float t = tg[n * TC + 0];

            const float bce = t * __logf(p) + (1.0f - t) * __logf(1.0f - p);
            const float mask = (t != 0.0f) ? 1.0f : 0.0f;

            const float lx = mask * o[n * OC + 1] - tg[n * TC + 1];
            const float ly = mask * o[n * OC + 2] - tg[n * TC + 2];

            const float sp  = mask * __fsqrt_rn(o[n * OC + 3]);
            const float lwh = sp - __fsqrt_rn(tg[n * TC + 3]);

            acc += 5.0f * (lx * lx + ly * ly) + 10.0f * (lwh * lwh) - 0.5f * bce;

            cls[n] = (int)tg[n * TC + 4];
            #pragma unroll
            for (int c = 0; c < 3; c++) l[n][c] = mask * o[n * OC + 4 + c];
        }

        // log_softmax over anchors per class column + NLL gather
        #pragma unroll
        for (int c = 0; c < 3; c++) {
            const float m = fmaxf(l[0][c], fmaxf(l[1][c], l[2][c]));
            const float s = __expf(l[0][c] - m) + __expf(l[1][c] - m) + __expf(l[2][c] - m);
            const float lse = m + __logf(s);
            const float sel = (cls[c] == 0) ? l[0][c] : ((cls[c] == 1) ? l[1][c] : l[2][c]);
            acc += 3.0f * (lse - sel);
        }
        __syncthreads();   // protect smem before next tile's staging
    }

    // -------- block reduction --------
    #pragma unroll
    for (int off = 16; off > 0; off >>= 1)
        acc += __shfl_xor_sync(0xFFFFFFFFu, acc, off);
    if ((tid & 31) == 0) wsum[tid >> 5] = acc;
    __syncthreads();

    if (tid == 0) {
        float s = 0.0f;
        #pragma unroll
        for (int w = 0; w < TPB / 32; w++) s += wsum[w];
        // relaxed double RMW at L2 (no L1 involvement)
        atomicAdd(&g_acc, (double)s);
        // acq_rel inc with wraparound -> orders the add, self-resets counter,
        // and gives the last block acquire visibility. NO threadfence (no L1D flush).
        unsigned int prev;
        asm volatile("atom.acq_rel.gpu.global.inc.u32 %0, [%1], %2;"
                     : "=r"(prev)
                     : "l"(&g_count), "r"((unsigned int)(GRID - 1))
                     : "memory");
        isLast = (prev == GRID - 1);
    }
    __syncthreads();

    if (isLast && tid == 0) {
        // atomic RMW read of the final total (always sees latest L2 value)
        unsigned long long bits =
            atomicAdd(reinterpret_cast<unsigned long long*>(&g_acc), 0ULL);
        const double tot = __longlong_as_double((long long)bits);
        out[0] = (float)(0.5 + tot / (double)((long long)B_TOTAL * NANCH));
        // reset accumulator for the next graph replay
        atomicExch(reinterpret_cast<unsigned long long*>(&g_acc), 0ULL);
    }
}

extern "C" void kernel_launch(void* const* d_in, const int* in_sizes, int n_in,
                              void* d_out, int out_size) {
    // Identify inputs by element count (output: B*21, target: B*15)
    const float* gout = (const float*)d_in[0];
    const float* gtgt = (const float*)d_in[1];
    if (n_in >= 2 && in_sizes[0] == B_TOTAL * NANCH * TC) {
        gout = (const float*)d_in[1];
        gtgt = (const float*)d_in[0];
    }

    ll_main_kernel<<<GRID, TPB>>>(gout, gtgt, (float*)d_out);
}

// round 4
// speedup vs baseline: 1.1587x; 1.0009x over previous
#include <cuda_runtime.h>

// LocalizationLoss fused single-pass reduction, single launch.
// One 256-batch tile per CTA (R1 streaming body) + in-kernel atomic finish.
// output: (B, 3, 7) f32 ; target: (B, 3, 5) f32 [presence, x, y, wh, cls]
// loss = 0.5 + mean_{b,n}[ 5*lx^2 + 5*ly^2 + 10*lwh^2 + 3*nll - 0.5*bce_term ]

#define B_TOTAL   1048576
#define NANCH     3
#define OC        7    // output channels
#define TC        5    // target channels
#define TPB       256  // threads per block == batches per block
#define NBLOCKS   (B_TOTAL / TPB)   // 4096

__device__ double       g_acc;     // zero at load; reset by last block each run
__device__ unsigned int g_count;   // wraps back to 0 via atom.inc

__global__ void __launch_bounds__(TPB) ll_main_kernel(const float* __restrict__ gout,
                                                      const float* __restrict__ gtgt,
                                                      float* __restrict__ out) {
    __shared__ float sOut[TPB * NANCH * OC];   // 21504 B
    __shared__ float sTgt[TPB * NANCH * TC];   // 15360 B
    __shared__ float wsum[TPB / 32];
    __shared__ bool  isLast;

    const int tid = threadIdx.x;
    const long long blockBase = (long long)blockIdx.x * TPB;

    // -------- coalesced float4 staging (spans are 16B-aligned) --------
    const float4* g4o = reinterpret_cast<const float4*>(gout + blockBase * (NANCH * OC));
    const float4* g4t = reinterpret_cast<const float4*>(gtgt + blockBase * (NANCH * TC));
    float4* s4o = reinterpret_cast<float4*>(sOut);
    float4* s4t = reinterpret_cast<float4*>(sTgt);

    constexpr int N4O = TPB * NANCH * OC / 4;  // 1344
    constexpr int N4T = TPB * NANCH * TC / 4;  //  960
    #pragma unroll
    for (int i = tid; i < N4O; i += TPB) s4o[i] = g4o[i];
    #pragma unroll
    for (int i = tid; i < N4T; i += TPB) s4t[i] = g4t[i];
    __syncthreads();

    // -------- per-batch loss terms (strides 21/15 odd -> conflict-free) --------
    const float* o  = sOut + tid * (NANCH * OC);
    const float* tg = sTgt + tid * (NANCH * TC);

    float acc = 0.0f;
    float l[NANCH][3];   // masked class logits, l[anchor][class]
    int   cls[NANCH];

    #pragma unroll
    for (int n = 0; n < NANCH; n++) {
        const float p = o[n * OC + 0];
        const float t = tg[n * TC + 0];

        // bce term: t*log(p) + (1-t)*log(1-p)
        const float bce = t * __logf(p) + (1.0f - t) * __logf(1.0f - p);

        const float mask = (t != 0.0f) ? 1.0f : 0.0f;

        const float lx = mask * o[n * OC + 1] - tg[n * TC + 1];
        const float ly = mask * o[n * OC + 2] - tg[n * TC + 2];

        // sq_pred = mask ? sqrt(out_wh) : 0   (out_wh in (0,1), sqrt always valid)
        const float sp  = mask * __fsqrt_rn(o[n * OC + 3]);
        const float lwh = sp - __fsqrt_rn(tg[n * TC + 3]);

        acc += 5.0f * (lx * lx + ly * ly) + 10.0f * (lwh * lwh) - 0.5f * bce;

        cls[n] = (int)tg[n * TC + 4];
        #pragma unroll
        for (int c = 0; c < 3; c++) l[n][c] = mask * o[n * OC + 4 + c];
    }

    // log_softmax over anchors (axis=1) per class column, then NLL gather
    #pragma unroll
    for (int c = 0; c < 3; c++) {
        const float m = fmaxf(l[0][c], fmaxf(l[1][c], l[2][c]));
        const float s = __expf(l[0][c] - m) + __expf(l[1][c] - m) + __expf(l[2][c] - m);
        const float lse = m + __logf(s);
        const float sel = (cls[c] == 0) ? l[0][c] : ((cls[c] == 1) ? l[1][c] : l[2][c]);
        acc += 3.0f * (lse - sel);
    }

    // -------- block reduction --------
    #pragma unroll
    for (int off = 16; off > 0; off >>= 1)
        acc += __shfl_xor_sync(0xFFFFFFFFu, acc, off);
    if ((tid & 31) == 0) wsum[tid >> 5] = acc;
    __syncthreads();

    if (tid == 0) {
        float s = 0.0f;
        #pragma unroll
        for (int w = 0; w < TPB / 32; w++) s += wsum[w];
        // relaxed double RMW at L2 (no L1 involvement, no CCTL.IVALL)
        atomicAdd(&g_acc, (double)s);
        // acq_rel inc with wraparound: orders the add, self-resets the counter,
        // gives the last block acquire visibility. NO threadfence.
        unsigned int prev;
        asm volatile("atom.acq_rel.gpu.global.inc.u32 %0, [%1], %2;"
                     : "=r"(prev)
                     : "l"(&g_count), "r"((unsigned int)(NBLOCKS - 1))
                     : "memory");
        isLast = (prev == NBLOCKS - 1);
    }
    __syncthreads();

    if (isLast && tid == 0) {
        // atomic read of the final total (RMW always sees latest L2 value)
        unsigned long long bits =
            atomicAdd(reinterpret_cast<unsigned long long*>(&g_acc), 0ULL);
        const double tot = __longlong_as_double((long long)bits);
        out[0] = (float)(0.5 + tot / (double)((long long)B_TOTAL * NANCH));
        // reset accumulator for the next graph replay (deterministic)
        atomicExch(reinterpret_cast<unsigned long long*>(&g_acc), 0ULL);
    }
}

extern "C" void kernel_launch(void* const* d_in, const int* in_sizes, int n_in,
                              void* d_out, int out_size) {
    // Identify inputs by element count (output: B*21, target: B*15)
    const float* gout = (const float*)d_in[0];
    const float* gtgt = (const float*)d_in[1];
    if (n_in >= 2 && in_sizes[0] == B_TOTAL * NANCH * TC) {
        gout = (const float*)d_in[1];
        gtgt = (const float*)d_in[0];
    }

    ll_main_kernel<<<NBLOCKS, TPB>>>(gout, gtgt, (float*)d_out);
}